// round 17
// baseline (speedup 1.0000x reference)
#include <cuda_runtime.h>
#include <cuda_bf16.h>
#include <math_constants.h>
#include <cstdint>

// Tropical (max-plus) matmul via log-sum-exp + bf16 mma.sync GEMM.
//   y[b,i] = mx_b + T*( ln( sum_j e^{(x_bj-mx_b)/T + CA} * e^{W_ij/T} ) - CA )
// T = 0.005, CA = 20.
//
// R13: split-K=4 GEMM. 128x64 CTA tile, 1024 threads (32 warps = 50% occ).
// Whole K=512 resident in smem (195 KB), loaded via one cp.async burst.
// Mainloop has ZERO barriers: group g (8 warps) crunches K[128g,128g+128).
// Partials combined through smem; ln epilogue; coalesced stores.

#define KDIM 512
#define NDIM 512
#define MAXB 2048
#define T_VAL 0.005f
#define CA_SHIFT 20.0f
#define C1_X 288.539008f   // (1/T)*log2(e)
#define C0_X 28.8539008f   // CA*log2(e)

__device__ float g_mx[MAXB];
__device__ __align__(16) __nv_bfloat16 g_Ax[MAXB * KDIM];
__device__ __align__(16) __nv_bfloat16 g_Bw[NDIM * KDIM];

__device__ __forceinline__ float ex2_approx(float t)
{ float r; asm("ex2.approx.f32 %0, %1;" : "=f"(r) : "f"(t)); return r; }

__device__ __forceinline__ float fast_ln(float v)
{
    int   iv = __float_as_int(v);
    float e  = (float)((iv >> 23) - 127);
    float m  = __int_as_float((iv & 0x7FFFFF) | 0x3F800000);
    float p  = -0.0565708f;
    p = fmaf(p, m,  0.4471796f);
    p = fmaf(p, m, -1.4699568f);
    p = fmaf(p, m,  2.8212026f);
    p = fmaf(p, m, -1.7417939f);
    return fmaf(e, 0.6931472f, p);
}

// ---------------- prep kernel: one warp per row, unique work only ----------

__global__ __launch_bounds__(256, 4) void prep_kernel(const float* __restrict__ x,
                                                      const float* __restrict__ w,
                                                      int Brows)
{
    const int gr   = blockIdx.x * 8 + (threadIdx.x >> 5);
    const int lane = threadIdx.x & 31;

    if (gr < Brows) {
        const float4* xr = (const float4*)(x + (size_t)gr * KDIM);
        float4 v[4];
        #pragma unroll
        for (int p = 0; p < 4; p++) v[p] = xr[lane + 32 * p];

        float m = -CUDART_INF_F;
        #pragma unroll
        for (int p = 0; p < 4; p++)
            m = fmaxf(m, fmaxf(fmaxf(v[p].x, v[p].y), fmaxf(v[p].z, v[p].w)));
        #pragma unroll
        for (int o = 16; o; o >>= 1) m = fmaxf(m, __shfl_xor_sync(0xffffffffu, m, o));
        if (lane == 0) g_mx[gr] = m;

        const float base = fmaf(-m, C1_X, C0_X);
        __nv_bfloat162* orow = (__nv_bfloat162*)(g_Ax + (size_t)gr * KDIM);
        #pragma unroll
        for (int p = 0; p < 4; p++) {
            float4 t = v[p];
            float e0 = ex2_approx(fmaf(t.x, C1_X, base));
            float e1 = ex2_approx(fmaf(t.y, C1_X, base));
            float e2 = ex2_approx(fmaf(t.z, C1_X, base));
            float e3 = ex2_approx(fmaf(t.w, C1_X, base));
            orow[(lane + 32 * p) * 2 + 0] = __floats2bfloat162_rn(e0, e1);
            orow[(lane + 32 * p) * 2 + 1] = __floats2bfloat162_rn(e2, e3);
        }
    } else {
        const int row = gr - Brows;
        if (row >= NDIM) return;
        const float4* wr = (const float4*)(w + (size_t)row * KDIM);
        __nv_bfloat162* orow = (__nv_bfloat162*)(g_Bw + (size_t)row * KDIM);
        #pragma unroll
        for (int p = 0; p < 4; p++) {
            float4 t = wr[lane + 32 * p];
            float e0 = ex2_approx(t.x * C1_X);
            float e1 = ex2_approx(t.y * C1_X);
            float e2 = ex2_approx(t.z * C1_X);
            float e3 = ex2_approx(t.w * C1_X);
            orow[(lane + 32 * p) * 2 + 0] = __floats2bfloat162_rn(e0, e1);
            orow[(lane + 32 * p) * 2 + 1] = __floats2bfloat162_rn(e2, e3);
        }
    }
}

// ---------------- GEMM helpers ----------------

__device__ __forceinline__ void cp16(uint32_t smem_addr, const void* gptr)
{
    asm volatile("cp.async.cg.shared.global [%0], [%1], 16;"
                 :: "r"(smem_addr), "l"(gptr));
}

__device__ __forceinline__ void ldsm_x4(uint32_t& r0, uint32_t& r1,
                                        uint32_t& r2, uint32_t& r3, uint32_t a)
{
    asm volatile("ldmatrix.sync.aligned.m8n8.x4.shared.b16 {%0,%1,%2,%3}, [%4];"
                 : "=r"(r0), "=r"(r1), "=r"(r2), "=r"(r3) : "r"(a));
}

__device__ __forceinline__ void mma_bf16(float* c, const uint32_t* a, uint32_t b0, uint32_t b1)
{
    asm volatile(
        "mma.sync.aligned.m16n8k16.row.col.f32.bf16.bf16.f32 "
        "{%0,%1,%2,%3},{%4,%5,%6,%7},{%8,%9},{%0,%1,%2,%3};"
        : "+f"(c[0]), "+f"(c[1]), "+f"(c[2]), "+f"(c[3])
        : "r"(a[0]), "r"(a[1]), "r"(a[2]), "r"(a[3]), "r"(b0), "r"(b1));
}

// smem map: row stride 1040 B (260 words ≡ 4 mod 32: LDSM conflict-free; 16B-aligned)
#define RSTR 1040
#define SM_A 0
#define SM_B (128 * RSTR)            // 133120
#define SM_TOT (SM_B + 64 * RSTR)    // 199680
// epilogue overlays (both inside [0, SM_TOT)):
#define SM_STG 0                     // 128 rows x 68 floats = 34816 B
#define SM_EX  34816                 // 3 groups x 8192 floats = 98304 B -> ends 133120

__global__ __launch_bounds__(1024)
void lse_gemm_kernel(float* __restrict__ out)
{
    extern __shared__ __align__(16) unsigned char sm[];

    const int tid  = threadIdx.x;
    const int warp = tid >> 5, lane = tid & 31;
    const int grp  = warp >> 3;           // K-group 0..3, owns K[128g, 128g+128)
    const int wg   = warp & 7;            // 4x2 grid within group
    const int wm   = wg & 3, wn = wg >> 2;
    const int bm   = blockIdx.y * 128, bn = blockIdx.x * 64;
    const int lr   = lane & 15;
    const int lh   = (lane >> 4) * 8;
    const uint32_t sbase = (uint32_t)__cvta_generic_to_shared(sm);

    float acc[2][4][4];
    #pragma unroll
    for (int i = 0; i < 2; i++)
        #pragma unroll
        for (int j = 0; j < 4; j++)
            #pragma unroll
            for (int k = 0; k < 4; k++) acc[i][j][k] = 0.f;

    // PDL: overlap setup with prep drain; block before first dependent load.
    cudaGridDependencySynchronize();

    // ---- load whole A (128x512) and B (64x512) tiles via cp.async ----
    #pragma unroll
    for (int j = 0; j < 8; j++) {          // A: 8192 chunks of 16B
        const int cid = tid + j * 1024;
        const int r = cid >> 6, c = cid & 63;
        cp16(sbase + SM_A + r * RSTR + c * 16, &g_Ax[(size_t)(bm + r) * KDIM + c * 8]);
    }
    #pragma unroll
    for (int j = 0; j < 4; j++) {          // B: 4096 chunks
        const int cid = tid + j * 1024;
        const int r = cid >> 6, c = cid & 63;
        cp16(sbase + SM_B + r * RSTR + c * 16, &g_Bw[(size_t)(bn + r) * KDIM + c * 8]);
    }
    asm volatile("cp.async.commit_group;" ::: "memory");
    asm volatile("cp.async.wait_group 0;" ::: "memory");
    __syncthreads();

    // ---- mainloop: 8 k16 steps over this group's 128 K-cols, NO barriers ----
    uint32_t abase[2], b0base, b1base;
    #pragma unroll
    for (int mt = 0; mt < 2; mt++)
        abase[mt] = sbase + SM_A + (wm * 32 + mt * 16 + lr) * RSTR + grp * 256 + lh * 2;
    b0base = sbase + SM_B + (wn * 32 +      lr) * RSTR + grp * 256 + lh * 2;
    b1base = sbase + SM_B + (wn * 32 + 16 + lr) * RSTR + grp * 256 + lh * 2;

    #pragma unroll
    for (int kk = 0; kk < 8; kk++) {
        const uint32_t off = (uint32_t)kk * 32u;
        uint32_t a0[4], a1[4], b0[4], b1[4];
        ldsm_x4(a0[0], a0[1], a0[2], a0[3], abase[0] + off);
        ldsm_x4(a1[0], a1[1], a1[2], a1[3], abase[1] + off);
        ldsm_x4(b0[0], b0[1], b0[2], b0[3], b0base + off);
        ldsm_x4(b1[0], b1[1], b1[2], b1[3], b1base + off);
        mma_bf16(acc[0][0], a0, b0[0], b0[2]);
        mma_bf16(acc[0][1], a0, b0[1], b0[3]);
        mma_bf16(acc[0][2], a0, b1[0], b1[2]);
        mma_bf16(acc[0][3], a0, b1[1], b1[3]);
        mma_bf16(acc[1][0], a1, b0[0], b0[2]);
        mma_bf16(acc[1][1], a1, b0[1], b0[3]);
        mma_bf16(acc[1][2], a1, b1[0], b1[2]);
        mma_bf16(acc[1][3], a1, b1[1], b1[3]);
    }
    __syncthreads();   // all smem reads done before epilogue overlays

    // ---- combine split-K quarters through smem ----
    float* ex = (float*)(sm + SM_EX);    // [grp-1][wg*32 + c][lane]
    if (grp != 0) {
        float* exg = ex + (size_t)(grp - 1) * 8192;
        #pragma unroll
        for (int mt = 0; mt < 2; mt++)
            #pragma unroll
            for (int nt = 0; nt < 4; nt++)
                #pragma unroll
                for (int k = 0; k < 4; k++)
                    exg[(wg * 32 + (mt * 4 + nt) * 4 + k) * 32 + lane] = acc[mt][nt][k];
    }
    __syncthreads();

    float* stg = (float*)(sm + SM_STG);  // 128 rows x 68 floats
    if (grp == 0) {
        #pragma unroll
        for (int mt = 0; mt < 2; mt++)
            #pragma unroll
            for (int nt = 0; nt < 4; nt++)
                #pragma unroll
                for (int k = 0; k < 4; k++) {
                    const int idx = (wg * 32 + (mt * 4 + nt) * 4 + k) * 32 + lane;
                    acc[mt][nt][k] += ex[idx] + ex[8192 + idx] + ex[16384 + idx];
                }

        const int g = lane >> 2, t4 = lane & 3;
        #pragma unroll
        for (int mt = 0; mt < 2; mt++) {
            const int r0 = wm * 32 + mt * 16 + g;
            const float mx0 = __ldg(&g_mx[bm + r0]);
            const float mx1 = __ldg(&g_mx[bm + r0 + 8]);
            #pragma unroll
            for (int nt = 0; nt < 4; nt++) {
                const int c0 = wn * 32 + nt * 8 + 2 * t4;
                stg[r0 * 68 + c0]           = mx0 + T_VAL * (fast_ln(acc[mt][nt][0]) - CA_SHIFT);
                stg[r0 * 68 + c0 + 1]       = mx0 + T_VAL * (fast_ln(acc[mt][nt][1]) - CA_SHIFT);
                stg[(r0 + 8) * 68 + c0]     = mx1 + T_VAL * (fast_ln(acc[mt][nt][2]) - CA_SHIFT);
                stg[(r0 + 8) * 68 + c0 + 1] = mx1 + T_VAL * (fast_ln(acc[mt][nt][3]) - CA_SHIFT);
            }
        }
    }
    __syncthreads();

    #pragma unroll
    for (int s = 0; s < 2; s++) {        // 2048 float4 chunks / 1024 threads
        const int i = tid + s * 1024;
        const int r = i >> 4, c4 = i & 15;
        float4 v = *(float4*)&stg[r * 68 + c4 * 4];
        *(float4*)&out[(size_t)(bm + r) * NDIM + bn + c4 * 4] = v;
    }
}

// ---------------- launch ----------------

extern "C" void kernel_launch(void* const* d_in, const int* in_sizes, int n_in,
                              void* d_out, int out_size)
{
    const float* x = (const float*)d_in[0];
    const float* W = (const float*)d_in[1];
    int nx = in_sizes[0], nw = in_sizes[1];
    if (nx == NDIM * KDIM && nw != NDIM * KDIM) {   // input-order safety
        const float* t = x; x = W; W = t;
        int ts = nx; nx = nw; nw = ts;
    }
    const int B = nx / KDIM;   // 2048

    const int prep_rows = B + NDIM;                   // 2560
    prep_kernel<<<(prep_rows + 7) / 8, 256>>>(x, W, B);

    cudaFuncSetAttribute(lse_gemm_kernel,
                         cudaFuncAttributeMaxDynamicSharedMemorySize, SM_TOT);

    cudaLaunchConfig_t cfg = {};
    cfg.gridDim  = dim3(NDIM / 64, B / 128, 1);       // (8,16) = 128 CTAs
    cfg.blockDim = dim3(1024, 1, 1);
    cfg.dynamicSmemBytes = SM_TOT;
    cfg.stream   = 0;
    cudaLaunchAttribute attr[1];
    attr[0].id = cudaLaunchAttributeProgrammaticStreamSerialization;
    attr[0].val.programmaticStreamSerializationAllowed = 1;
    cfg.attrs = attr;
    cfg.numAttrs = 1;
    cudaError_t e = cudaLaunchKernelEx(&cfg, lse_gemm_kernel, (float*)d_out);
    if (e != cudaSuccess) {
        dim3 grid(NDIM / 64, B / 128);
        lse_gemm_kernel<<<grid, 1024, SM_TOT>>>((float*)d_out);
    }
}